// round 1
// baseline (speedup 1.0000x reference)
#include <cuda_runtime.h>

// GCN: N=100000 nodes, E=3200000 edges, 29 -> 64 -> 2
#define NN  100000
#define ME  3200000
#define IND 29
#define HID 64

// ---- scratch (device globals; no runtime allocation) ----
__device__ float g_deg [NN];
__device__ float g_dinv[NN];
__device__ int   g_src [ME];
__device__ int   g_dst [ME];
__device__ float g_h1  [NN * HID];   // x @ W1
__device__ float g_agg1[NN * HID];   // layer-1 aggregation accumulator
__device__ float g_h2  [NN * 2];     // relu(h_post) @ W2
__device__ int   g_is64;

// ---------------------------------------------------------------------------
// K0: deg = 1 (self loop) for all nodes; thread 0 detects edge dtype.
// If edge_index is int32, reading it as int64 packs two indices per word:
// the value is >= 2^32 unless the high index is 0 (prob ~1e-5 per sample).
// 16 samples -> unambiguous.
// ---------------------------------------------------------------------------
__global__ void k_init(const long long* __restrict__ ei, int E, int n) {
    int i = blockIdx.x * blockDim.x + threadIdx.x;
    if (i < n) g_deg[i] = 1.0f;
    if (i == 0) {
        int is64 = 1;
        #pragma unroll
        for (int t = 0; t < 16; t++) {
            long long v = ei[t];
            if (v < 0 || v >= (long long)n) { is64 = 0; break; }
        }
        g_is64 = is64;
    }
}

// ---------------------------------------------------------------------------
// K1: convert edges to int32 (cached for both layers) + count in-degrees.
// ---------------------------------------------------------------------------
__global__ void k_prep(const void* __restrict__ eiv, int E) {
    int i = blockIdx.x * blockDim.x + threadIdx.x;
    if (i >= E) return;
    int s, d;
    if (g_is64) {
        const long long* e = (const long long*)eiv;
        s = (int)e[i];
        d = (int)e[E + i];
    } else {
        const int* e = (const int*)eiv;
        s = e[i];
        d = e[E + i];
    }
    g_src[i] = s;
    g_dst[i] = d;
    atomicAdd(&g_deg[d], 1.0f);   // integer counts, exact in fp32
}

// ---------------------------------------------------------------------------
// K2: dinv = rsqrt(deg)   (deg >= 1 always, self loops)
// ---------------------------------------------------------------------------
__global__ void k_dinv(int n) {
    int i = blockIdx.x * blockDim.x + threadIdx.x;
    if (i < n) g_dinv[i] = rsqrtf(g_deg[i]);
}

// ---------------------------------------------------------------------------
// K3: h1 = x @ W1 ; agg1 init = dinv^2 * h1 (self-loop message folded in).
// One thread per (node, j). W1 (29x64 = 7.4 KB) staged in shared.
// ---------------------------------------------------------------------------
__global__ void k_gemm1(const float* __restrict__ x,
                        const float* __restrict__ W1, int n) {
    __shared__ float sW[IND * HID];
    for (int t = threadIdx.x; t < IND * HID; t += blockDim.x) sW[t] = W1[t];
    __syncthreads();

    int idx  = blockIdx.x * blockDim.x + threadIdx.x;
    int node = idx >> 6;
    int j    = idx & 63;
    if (node >= n) return;

    const float* xr = x + node * IND;
    float s = 0.0f;
    #pragma unroll
    for (int k = 0; k < IND; k++) s = fmaf(xr[k], sW[k * HID + j], s);

    g_h1[idx] = s;
    float di = g_dinv[node];
    g_agg1[idx] = di * di * s;
}

// ---------------------------------------------------------------------------
// K4: layer-1 edge scatter. 16 threads per edge, one float4 each.
// red.global.add.v4.f32 -> 16 atomic instructions per edge (vs 64 scalar).
// ---------------------------------------------------------------------------
__global__ void k_edge1(int E) {
    int t = blockIdx.x * blockDim.x + threadIdx.x;
    int e = t >> 4;
    int c = t & 15;
    if (e >= E) return;

    int s = g_src[e];
    int d = g_dst[e];
    float nrm = g_dinv[s] * g_dinv[d];

    float4 v = *(const float4*)&g_h1[s * HID + c * 4];
    v.x *= nrm; v.y *= nrm; v.z *= nrm; v.w *= nrm;

    float* p = &g_agg1[d * HID + c * 4];
    asm volatile("red.global.add.v4.f32 [%0], {%1, %2, %3, %4};"
                 :: "l"(p), "f"(v.x), "f"(v.y), "f"(v.z), "f"(v.w)
                 : "memory");
}

// ---------------------------------------------------------------------------
// K5: per-node epilogue+GEMM2, fused: one warp per node.
//   v = relu(agg1 + b1);  h2 = v @ W2;  out = dinv^2 * h2 + b2  (self-loop +
//   bias init for layer-2 accumulation, written before edge pass 2).
// Each lane handles j and j+32; warp-reduce the two dot products.
// ---------------------------------------------------------------------------
__global__ void k_post1(const float* __restrict__ b1,
                        const float* __restrict__ W2,
                        const float* __restrict__ b2,
                        float* __restrict__ out, int n) {
    int gtid = blockIdx.x * blockDim.x + threadIdx.x;
    int node = gtid >> 5;
    int lane = gtid & 31;
    if (node >= n) return;

    float p0 = 0.0f, p1 = 0.0f;
    #pragma unroll
    for (int r = 0; r < 2; r++) {
        int j = lane + r * 32;
        float v = g_agg1[node * HID + j] + b1[j];
        v = fmaxf(v, 0.0f);
        p0 = fmaf(v, W2[j * 2 + 0], p0);
        p1 = fmaf(v, W2[j * 2 + 1], p1);
    }
    #pragma unroll
    for (int o = 16; o > 0; o >>= 1) {
        p0 += __shfl_xor_sync(0xFFFFFFFFu, p0, o);
        p1 += __shfl_xor_sync(0xFFFFFFFFu, p1, o);
    }
    if (lane == 0) {
        g_h2[node * 2 + 0] = p0;
        g_h2[node * 2 + 1] = p1;
        float di = g_dinv[node];
        float w  = di * di;
        out[node * 2 + 0] = w * p0 + b2[0];
        out[node * 2 + 1] = w * p1 + b2[1];
    }
}

// ---------------------------------------------------------------------------
// K6: layer-2 edge scatter. One thread per edge (only 2 floats / edge).
// ---------------------------------------------------------------------------
__global__ void k_edge2(float* __restrict__ out, int E) {
    int e = blockIdx.x * blockDim.x + threadIdx.x;
    if (e >= E) return;

    int s = g_src[e];
    int d = g_dst[e];
    float nrm = g_dinv[s] * g_dinv[d];

    float2 h = *(const float2*)&g_h2[s * 2];
    float m0 = h.x * nrm;
    float m1 = h.y * nrm;

    float* p = &out[d * 2];
    asm volatile("red.global.add.v2.f32 [%0], {%1, %2};"
                 :: "l"(p), "f"(m0), "f"(m1)
                 : "memory");
}

// ---------------------------------------------------------------------------
extern "C" void kernel_launch(void* const* d_in, const int* in_sizes, int n_in,
                              void* d_out, int out_size) {
    const float* x  = (const float*)d_in[0];
    const void*  ei = d_in[1];
    const float* W1 = (const float*)d_in[2];
    const float* b1 = (const float*)d_in[3];
    const float* W2 = (const float*)d_in[4];
    const float* b2 = (const float*)d_in[5];
    float*       out = (float*)d_out;

    int n = in_sizes[0] / IND;   // 100000
    int E = in_sizes[1] / 2;     // 3200000

    const int TB = 256;
    k_init <<<(n + TB - 1) / TB, TB>>>((const long long*)ei, E, n);
    k_prep <<<(E + TB - 1) / TB, TB>>>(ei, E);
    k_dinv <<<(n + TB - 1) / TB, TB>>>(n);
    k_gemm1<<<(n * HID + TB - 1) / TB, TB>>>(x, W1, n);
    k_edge1<<<((E * 16) + TB - 1) / TB, TB>>>(E);
    k_post1<<<(n * 32 + TB - 1) / TB, TB>>>(b1, W2, b2, out, n);
    k_edge2<<<(E + TB - 1) / TB, TB>>>(out, E);
}

// round 2
// speedup vs baseline: 1.5023x; 1.5023x over previous
#include <cuda_runtime.h>

// GCN: N=100000 nodes, E=3200000 edges, 29 -> 64 -> 2
// Layer 1 restructured: aggregate raw x (29 dims, padded to 32) FIRST, then
// transform: A(xW1) == (Ax)W1. Halves edge-pass traffic vs 64-dim hidden.
#define NN  100000
#define ME  3200000
#define IND 29
#define PAD 32
#define HID 64

// ---- scratch (device globals; no runtime allocation) ----
__device__ float g_deg [NN];
__device__ float g_dinv[NN];
__device__ int   g_src [ME];
__device__ int   g_dst [ME];
__device__ float g_xp  [NN * PAD];   // x padded to 32 cols (zeros in 29..31)
__device__ float g_aggx[NN * PAD];   // layer-1 aggregation of raw features
__device__ float g_h2  [NN * 2];     // relu(h) @ W2 per node
__device__ int   g_is64;

// ---------------------------------------------------------------------------
// K0: deg = 1 (self loop) for all nodes; thread 0 detects edge dtype.
// int32 edges read as int64 pack two indices -> value >= 2^32 almost surely.
// ---------------------------------------------------------------------------
__global__ void k_init(const long long* __restrict__ ei, int E, int n) {
    int i = blockIdx.x * blockDim.x + threadIdx.x;
    if (i < n) g_deg[i] = 1.0f;
    if (i == 0) {
        int is64 = 1;
        #pragma unroll
        for (int t = 0; t < 16; t++) {
            long long v = ei[t];
            if (v < 0 || v >= (long long)n) { is64 = 0; break; }
        }
        g_is64 = is64;
    }
}

// ---------------------------------------------------------------------------
// K1: convert edges to int32 (cached for both passes) + count in-degrees.
// ---------------------------------------------------------------------------
__global__ void k_prep(const void* __restrict__ eiv, int E) {
    int i = blockIdx.x * blockDim.x + threadIdx.x;
    if (i >= E) return;
    int s, d;
    if (g_is64) {
        const long long* e = (const long long*)eiv;
        s = (int)e[i];
        d = (int)e[E + i];
    } else {
        const int* e = (const int*)eiv;
        s = e[i];
        d = e[E + i];
    }
    g_src[i] = s;
    g_dst[i] = d;
    atomicAdd(&g_deg[d], 1.0f);   // integer counts, exact in fp32
}

// ---------------------------------------------------------------------------
// K2: dinv = rsqrt(deg)
// ---------------------------------------------------------------------------
__global__ void k_dinv(int n) {
    int i = blockIdx.x * blockDim.x + threadIdx.x;
    if (i < n) g_dinv[i] = rsqrtf(g_deg[i]);
}

// ---------------------------------------------------------------------------
// K3: pad x to 32 cols + init accumulator with self-loop msg dinv^2 * x.
// 32 threads per node (one warp) -> same dinv broadcast within warp.
// ---------------------------------------------------------------------------
__global__ void k_pad(const float* __restrict__ x, int n) {
    int idx  = blockIdx.x * blockDim.x + threadIdx.x;
    int node = idx >> 5;
    int c    = idx & 31;
    if (node >= n) return;
    float v  = (c < IND) ? x[node * IND + c] : 0.0f;
    float di = g_dinv[node];
    g_xp  [idx] = v;
    g_aggx[idx] = di * di * v;
}

// ---------------------------------------------------------------------------
// K4: layer-1 edge scatter on 32-float padded rows. 8 threads/edge,
// one float4 each; red.global.add.v4.f32 -> 8 atomic instrs per edge.
// ---------------------------------------------------------------------------
__global__ void k_edge1(int E) {
    int t = blockIdx.x * blockDim.x + threadIdx.x;
    int e = t >> 3;
    int c = t & 7;
    if (e >= E) return;

    int s = g_src[e];
    int d = g_dst[e];
    float nrm = g_dinv[s] * g_dinv[d];

    float4 v = *(const float4*)&g_xp[s * PAD + c * 4];
    v.x *= nrm; v.y *= nrm; v.z *= nrm; v.w *= nrm;

    float* p = &g_aggx[d * PAD + c * 4];
    asm volatile("red.global.add.v4.f32 [%0], {%1, %2, %3, %4};"
                 :: "l"(p), "f"(v.x), "f"(v.y), "f"(v.z), "f"(v.w)
                 : "memory");
}

// ---------------------------------------------------------------------------
// K5: fused transform: h = relu(aggx @ W1 + b1); h2 = h @ W2;
//     out = dinv^2 * h2 + b2  (layer-2 self-loop + bias init).
// One warp per node. x row held one element per lane, broadcast via shfl.
// Each lane owns hidden cols (lane, lane+32).
// ---------------------------------------------------------------------------
__global__ void k_fused(const float* __restrict__ W1,
                        const float* __restrict__ b1,
                        const float* __restrict__ W2,
                        const float* __restrict__ b2,
                        float* __restrict__ out, int n) {
    __shared__ float sW1[IND * HID];
    __shared__ float sb1[HID];
    __shared__ float sW2[HID * 2];
    for (int t = threadIdx.x; t < IND * HID; t += blockDim.x) sW1[t] = W1[t];
    if (threadIdx.x < HID)     sb1[threadIdx.x] = b1[threadIdx.x];
    if (threadIdx.x < HID * 2) sW2[threadIdx.x] = W2[threadIdx.x];
    __syncthreads();

    int gt   = blockIdx.x * blockDim.x + threadIdx.x;
    int node = gt >> 5;
    int lane = gt & 31;
    if (node >= n) return;

    float xv = g_aggx[node * PAD + lane];   // lanes 29..31 hold zeros

    float h0 = sb1[lane];
    float h1 = sb1[lane + 32];
    #pragma unroll
    for (int k = 0; k < IND; k++) {
        float xk = __shfl_sync(0xFFFFFFFFu, xv, k);
        h0 = fmaf(xk, sW1[k * HID + lane],      h0);
        h1 = fmaf(xk, sW1[k * HID + lane + 32], h1);
    }
    h0 = fmaxf(h0, 0.0f);
    h1 = fmaxf(h1, 0.0f);

    float p0 = h0 * sW2[lane * 2]     + h1 * sW2[(lane + 32) * 2];
    float p1 = h0 * sW2[lane * 2 + 1] + h1 * sW2[(lane + 32) * 2 + 1];
    #pragma unroll
    for (int o = 16; o > 0; o >>= 1) {
        p0 += __shfl_xor_sync(0xFFFFFFFFu, p0, o);
        p1 += __shfl_xor_sync(0xFFFFFFFFu, p1, o);
    }
    if (lane == 0) {
        g_h2[node * 2 + 0] = p0;
        g_h2[node * 2 + 1] = p1;
        float di = g_dinv[node];
        float w  = di * di;
        out[node * 2 + 0] = w * p0 + b2[0];
        out[node * 2 + 1] = w * p1 + b2[1];
    }
}

// ---------------------------------------------------------------------------
// K6: layer-2 edge scatter. One thread per edge (2 floats / edge).
// ---------------------------------------------------------------------------
__global__ void k_edge2(float* __restrict__ out, int E) {
    int e = blockIdx.x * blockDim.x + threadIdx.x;
    if (e >= E) return;

    int s = g_src[e];
    int d = g_dst[e];
    float nrm = g_dinv[s] * g_dinv[d];

    float2 h = *(const float2*)&g_h2[s * 2];
    float m0 = h.x * nrm;
    float m1 = h.y * nrm;

    float* p = &out[d * 2];
    asm volatile("red.global.add.v2.f32 [%0], {%1, %2};"
                 :: "l"(p), "f"(m0), "f"(m1)
                 : "memory");
}

// ---------------------------------------------------------------------------
extern "C" void kernel_launch(void* const* d_in, const int* in_sizes, int n_in,
                              void* d_out, int out_size) {
    const float* x  = (const float*)d_in[0];
    const void*  ei = d_in[1];
    const float* W1 = (const float*)d_in[2];
    const float* b1 = (const float*)d_in[3];
    const float* W2 = (const float*)d_in[4];
    const float* b2 = (const float*)d_in[5];
    float*       out = (float*)d_out;

    int n = in_sizes[0] / IND;   // 100000
    int E = in_sizes[1] / 2;     // 3200000

    const int TB = 256;
    k_init <<<(n + TB - 1) / TB, TB>>>((const long long*)ei, E, n);
    k_prep <<<(E + TB - 1) / TB, TB>>>(ei, E);
    k_dinv <<<(n + TB - 1) / TB, TB>>>(n);
    k_pad  <<<(n * PAD + TB - 1) / TB, TB>>>(x, n);
    k_edge1<<<((E * 8) + TB - 1) / TB, TB>>>(E);
    k_fused<<<(n * 32 + TB - 1) / TB, TB>>>(W1, b1, W2, b2, out, n);
    k_edge2<<<(E + TB - 1) / TB, TB>>>(out, E);
}

// round 3
// speedup vs baseline: 1.6276x; 1.0835x over previous
#include <cuda_runtime.h>

// GCN: N=100000, E=3200000, 29 -> 64 -> 2.
// Strategy: build dst-bucketed CSR once (count -> scan -> scatter), then both
// aggregation passes are gather-only (zero atomics, one store per node).
// Layer 1 aggregates RAW features (A(xW1) == (Ax)W1), 32-float padded rows.
#define NN  100000
#define ME  3200000
#define IND 29
#define PAD 32
#define HID 64
#define NBMAX 400            // ceil(NN/256) = 391

// ---- scratch (device globals) ----
__device__ int   g_deg    [NN];        // in-degree (real edges only)
__device__ float g_dinv   [NN];        // rsqrt(deg+1)
__device__ int   g_rowst  [NN];        // CSR row starts (exclusive scan of deg)
__device__ int   g_cursor [NN];        // insertion cursors
__device__ int   g_csr    [ME];        // src node per edge, bucketed by dst
__device__ int   g_bsum   [NBMAX];
__device__ int   g_boff   [NBMAX];
__device__ float g_xp     [NN * PAD];  // dinv[s] * x[s], padded to 32
__device__ float g_aggx   [NN * PAD];  // aggregated layer-1 features
__device__ float g_h2     [NN * 2];    // dinv[s] * (relu(y W1 + b1) W2)
__device__ int   g_is64;

// ---------------------------------------------------------------------------
// K0: zero degree counters; thread 0 detects edge dtype (int32 read as int64
// packs two indices -> value out of [0,n) almost surely).
// ---------------------------------------------------------------------------
__global__ void k_init(const long long* __restrict__ ei, int n) {
    int i = blockIdx.x * blockDim.x + threadIdx.x;
    if (i < n) g_deg[i] = 0;
    if (i == 0) {
        int is64 = 1;
        #pragma unroll
        for (int t = 0; t < 16; t++) {
            long long v = ei[t];
            if (v < 0 || v >= (long long)n) { is64 = 0; break; }
        }
        g_is64 = is64;
    }
}

__device__ __forceinline__ int edge_dst(const void* eiv, int E, int i) {
    if (g_is64) return (int)((const long long*)eiv)[E + i];
    return ((const int*)eiv)[E + i];
}
__device__ __forceinline__ int edge_src(const void* eiv, int E, int i) {
    if (g_is64) return (int)((const long long*)eiv)[i];
    return ((const int*)eiv)[i];
}

// K1: count in-degrees.
__global__ void k_count(const void* __restrict__ eiv, int E) {
    int i = blockIdx.x * blockDim.x + threadIdx.x;
    if (i >= E) return;
    atomicAdd(&g_deg[edge_dst(eiv, E, i)], 1);
}

// K2a: per-block sums of deg (256 per block).
__global__ void k_scanA(int n) {
    __shared__ int sh[256];
    int t = threadIdx.x;
    int i = blockIdx.x * 256 + t;
    sh[t] = (i < n) ? g_deg[i] : 0;
    __syncthreads();
    for (int o = 128; o > 0; o >>= 1) {
        if (t < o) sh[t] += sh[t + o];
        __syncthreads();
    }
    if (t == 0) g_bsum[blockIdx.x] = sh[0];
}

// K2b: exclusive scan of block sums (single block, nb <= 512).
__global__ void k_scanB(int nb) {
    __shared__ int sh[512];
    int t = threadIdx.x;
    int v = (t < nb) ? g_bsum[t] : 0;
    sh[t] = v;
    __syncthreads();
    for (int o = 1; o < 512; o <<= 1) {
        int a = (t >= o) ? sh[t - o] : 0;
        __syncthreads();
        sh[t] += a;
        __syncthreads();
    }
    if (t < nb) g_boff[t] = sh[t] - v;   // exclusive
}

// K2c: row starts + cursors + dinv.
__global__ void k_scanC(int n) {
    __shared__ int sh[256];
    int t = threadIdx.x;
    int i = blockIdx.x * 256 + t;
    int v = (i < n) ? g_deg[i] : 0;
    sh[t] = v;
    __syncthreads();
    for (int o = 1; o < 256; o <<= 1) {
        int a = (t >= o) ? sh[t - o] : 0;
        __syncthreads();
        sh[t] += a;
        __syncthreads();
    }
    if (i < n) {
        int rs = g_boff[blockIdx.x] + sh[t] - v;
        g_rowst [i] = rs;
        g_cursor[i] = rs;
        g_dinv  [i] = rsqrtf((float)(v + 1));   // +1 self loop
    }
}

// K3: scatter edges into dst-bucketed CSR (src only; norm folded into xp).
__global__ void k_scatter(const void* __restrict__ eiv, int E) {
    int i = blockIdx.x * blockDim.x + threadIdx.x;
    if (i >= E) return;
    int s = edge_src(eiv, E, i);
    int d = edge_dst(eiv, E, i);
    int pos = atomicAdd(&g_cursor[d], 1);
    g_csr[pos] = s;
}

// K4: xp = dinv[node] * x[node], padded to 32 cols (warp per node).
__global__ void k_pad(const float* __restrict__ x, int n) {
    int idx  = blockIdx.x * blockDim.x + threadIdx.x;
    int node = idx >> 5;
    int c    = idx & 31;
    if (node >= n) return;
    float v = (c < IND) ? x[node * IND + c] : 0.0f;
    g_xp[idx] = g_dinv[node] * v;
}

// ---------------------------------------------------------------------------
// K5: layer-1 gather. One warp per dst node; lane owns one of 32 columns.
//   y[d] = dinv[d] * ( xp[d] + sum_{s in in(d)} xp[s] )    (no atomics)
// Edge list batch-loaded coalesced, broadcast via shfl.
// ---------------------------------------------------------------------------
__global__ void k_gather1(int n) {
    int gt   = blockIdx.x * blockDim.x + threadIdx.x;
    int d    = gt >> 5;
    int lane = gt & 31;
    if (d >= n) return;

    int start = g_rowst[d];
    int cnt   = g_deg[d];

    float acc = g_xp[d * PAD + lane];          // self loop (pre-scaled)
    for (int base = 0; base < cnt; base += 32) {
        int rem = cnt - base;
        int m   = rem < 32 ? rem : 32;
        int s   = (lane < m) ? g_csr[start + base + lane] : 0;
        #pragma unroll 4
        for (int j = 0; j < m; j++) {
            int sj = __shfl_sync(0xFFFFFFFFu, s, j);
            acc += g_xp[sj * PAD + lane];
        }
    }
    g_aggx[d * PAD + lane] = g_dinv[d] * acc;
}

// ---------------------------------------------------------------------------
// K6: fused transform. One warp per node:
//   h  = relu(y @ W1 + b1);  h2s = dinv * (h @ W2)
// ---------------------------------------------------------------------------
__global__ void k_fused(const float* __restrict__ W1,
                        const float* __restrict__ b1,
                        const float* __restrict__ W2,
                        int n) {
    __shared__ float sW1[IND * HID];
    __shared__ float sb1[HID];
    __shared__ float sW2[HID * 2];
    for (int t = threadIdx.x; t < IND * HID; t += blockDim.x) sW1[t] = W1[t];
    if (threadIdx.x < HID)     sb1[threadIdx.x] = b1[threadIdx.x];
    if (threadIdx.x < HID * 2) sW2[threadIdx.x] = W2[threadIdx.x];
    __syncthreads();

    int gt   = blockIdx.x * blockDim.x + threadIdx.x;
    int node = gt >> 5;
    int lane = gt & 31;
    if (node >= n) return;

    float yv = g_aggx[node * PAD + lane];   // lanes 29..31 zero

    float h0 = sb1[lane];
    float h1 = sb1[lane + 32];
    #pragma unroll
    for (int k = 0; k < IND; k++) {
        float yk = __shfl_sync(0xFFFFFFFFu, yv, k);
        h0 = fmaf(yk, sW1[k * HID + lane],      h0);
        h1 = fmaf(yk, sW1[k * HID + lane + 32], h1);
    }
    h0 = fmaxf(h0, 0.0f);
    h1 = fmaxf(h1, 0.0f);

    float p0 = h0 * sW2[lane * 2]     + h1 * sW2[(lane + 32) * 2];
    float p1 = h0 * sW2[lane * 2 + 1] + h1 * sW2[(lane + 32) * 2 + 1];
    #pragma unroll
    for (int o = 16; o > 0; o >>= 1) {
        p0 += __shfl_xor_sync(0xFFFFFFFFu, p0, o);
        p1 += __shfl_xor_sync(0xFFFFFFFFu, p1, o);
    }
    if (lane == 0) {
        float di = g_dinv[node];
        g_h2[node * 2 + 0] = di * p0;
        g_h2[node * 2 + 1] = di * p1;
    }
}

// ---------------------------------------------------------------------------
// K7: layer-2 gather + output. One warp per dst; lanes strided over edges.
//   out[d] = dinv[d] * ( h2s[d] + sum_{s} h2s[s] ) + b2
// ---------------------------------------------------------------------------
__global__ void k_gather2(const float* __restrict__ b2,
                          float* __restrict__ out, int n) {
    int gt   = blockIdx.x * blockDim.x + threadIdx.x;
    int d    = gt >> 5;
    int lane = gt & 31;
    if (d >= n) return;

    int start = g_rowst[d];
    int cnt   = g_deg[d];

    float p0 = 0.0f, p1 = 0.0f;
    for (int i = start + lane; i < start + cnt; i += 32) {
        int s = g_csr[i];
        float2 h = *(const float2*)&g_h2[s * 2];
        p0 += h.x;
        p1 += h.y;
    }
    #pragma unroll
    for (int o = 16; o > 0; o >>= 1) {
        p0 += __shfl_xor_sync(0xFFFFFFFFu, p0, o);
        p1 += __shfl_xor_sync(0xFFFFFFFFu, p1, o);
    }
    if (lane == 0) {
        float2 hd = *(const float2*)&g_h2[d * 2];
        float di = g_dinv[d];
        out[d * 2 + 0] = di * (p0 + hd.x) + b2[0];
        out[d * 2 + 1] = di * (p1 + hd.y) + b2[1];
    }
}

// ---------------------------------------------------------------------------
extern "C" void kernel_launch(void* const* d_in, const int* in_sizes, int n_in,
                              void* d_out, int out_size) {
    const float* x  = (const float*)d_in[0];
    const void*  ei = d_in[1];
    const float* W1 = (const float*)d_in[2];
    const float* b1 = (const float*)d_in[3];
    const float* W2 = (const float*)d_in[4];
    const float* b2 = (const float*)d_in[5];
    float*       out = (float*)d_out;

    int n = in_sizes[0] / IND;   // 100000
    int E = in_sizes[1] / 2;     // 3200000
    int nb = (n + 255) / 256;    // 391

    const int TB = 256;
    k_init   <<<(n + TB - 1) / TB, TB>>>((const long long*)ei, n);
    k_count  <<<(E + TB - 1) / TB, TB>>>(ei, E);
    k_scanA  <<<nb, 256>>>(n);
    k_scanB  <<<1, 512>>>(nb);
    k_scanC  <<<nb, 256>>>(n);
    k_scatter<<<(E + TB - 1) / TB, TB>>>(ei, E);
    k_pad    <<<(n * PAD + TB - 1) / TB, TB>>>(x, n);
    k_gather1<<<(n * 32 + TB - 1) / TB, TB>>>(n);
    k_fused  <<<(n * 32 + TB - 1) / TB, TB>>>(W1, b1, W2, n);
    k_gather2<<<(n * 32 + TB - 1) / TB, TB>>>(b2, out, n);
}

// round 4
// speedup vs baseline: 1.6743x; 1.0287x over previous
#include <cuda_runtime.h>
#include <cuda_fp16.h>

// GCN: N=100000, E=3200000, 29 -> 64 -> 2.
// dst-bucketed CSR (count -> scan -> scatter), then gather-only passes.
// Layer 1 aggregates RAW features (A(xW1) == (Ax)W1) stored as fp16
// (64 B/row) with fp32 accumulation.
#define NN  100000
#define ME  3200000
#define IND 29
#define PAD 32
#define HID 64
#define NBMAX 400            // ceil(NN/256) = 391

// ---- scratch (device globals) ----
__device__ int     g_deg    [NN];         // in-degree (real edges only)
__device__ float   g_dinv   [NN];         // rsqrt(deg+1)
__device__ int     g_rowst  [NN];         // CSR row starts
__device__ int     g_cursor [NN];         // insertion cursors
__device__ int     g_csr    [ME];         // src per edge, bucketed by dst
__device__ int     g_bsum   [NBMAX];
__device__ int     g_boff   [NBMAX];
__device__ __half2 g_xp     [NN * 16];    // dinv[s]*x[s] fp16, 16 half2/row
__device__ float   g_aggx   [NN * PAD];   // aggregated layer-1 features
__device__ float   g_h2     [NN * 2];     // dinv[s]*(relu(y W1+b1) W2)
__device__ int     g_is64;

// ---------------------------------------------------------------------------
// K0: zero degree counters; thread 0 detects edge dtype (int32 read as int64
// packs two indices -> value out of [0,n) almost surely).
// ---------------------------------------------------------------------------
__global__ void k_init(const long long* __restrict__ ei, int n) {
    int i = blockIdx.x * blockDim.x + threadIdx.x;
    if (i < n) g_deg[i] = 0;
    if (i == 0) {
        int is64 = 1;
        #pragma unroll
        for (int t = 0; t < 16; t++) {
            long long v = ei[t];
            if (v < 0 || v >= (long long)n) { is64 = 0; break; }
        }
        g_is64 = is64;
    }
}

__device__ __forceinline__ int edge_dst(const void* eiv, int E, int i) {
    if (g_is64) return (int)((const long long*)eiv)[E + i];
    return ((const int*)eiv)[E + i];
}
__device__ __forceinline__ int edge_src(const void* eiv, int E, int i) {
    if (g_is64) return (int)((const long long*)eiv)[i];
    return ((const int*)eiv)[i];
}

// K1: count in-degrees.
__global__ void k_count(const void* __restrict__ eiv, int E) {
    int i = blockIdx.x * blockDim.x + threadIdx.x;
    if (i >= E) return;
    atomicAdd(&g_deg[edge_dst(eiv, E, i)], 1);
}

// K2a: per-block sums of deg (256 per block).
__global__ void k_scanA(int n) {
    __shared__ int sh[256];
    int t = threadIdx.x;
    int i = blockIdx.x * 256 + t;
    sh[t] = (i < n) ? g_deg[i] : 0;
    __syncthreads();
    for (int o = 128; o > 0; o >>= 1) {
        if (t < o) sh[t] += sh[t + o];
        __syncthreads();
    }
    if (t == 0) g_bsum[blockIdx.x] = sh[0];
}

// K2b: exclusive scan of block sums — single warp, shfl scan.
__global__ void k_scanB(int nb) {
    int lane = threadIdx.x;
    int carry = 0;
    for (int base = 0; base < nb; base += 32) {
        int v = (base + lane < nb) ? g_bsum[base + lane] : 0;
        int s = v;
        #pragma unroll
        for (int o = 1; o < 32; o <<= 1) {
            int t = __shfl_up_sync(0xFFFFFFFFu, s, o);
            if (lane >= o) s += t;
        }
        if (base + lane < nb) g_boff[base + lane] = carry + s - v;
        carry += __shfl_sync(0xFFFFFFFFu, s, 31);
    }
}

// K2c: row starts + cursors + dinv.
__global__ void k_scanC(int n) {
    __shared__ int sh[256];
    int t = threadIdx.x;
    int i = blockIdx.x * 256 + t;
    int v = (i < n) ? g_deg[i] : 0;
    sh[t] = v;
    __syncthreads();
    for (int o = 1; o < 256; o <<= 1) {
        int a = (t >= o) ? sh[t - o] : 0;
        __syncthreads();
        sh[t] += a;
        __syncthreads();
    }
    if (i < n) {
        int rs = g_boff[blockIdx.x] + sh[t] - v;
        g_rowst [i] = rs;
        g_cursor[i] = rs;
        g_dinv  [i] = rsqrtf((float)(v + 1));   // +1 self loop
    }
}

// K3: scatter edges into dst-bucketed CSR.
__global__ void k_scatter(const void* __restrict__ eiv, int E) {
    int i = blockIdx.x * blockDim.x + threadIdx.x;
    if (i >= E) return;
    int s = edge_src(eiv, E, i);
    int d = edge_dst(eiv, E, i);
    int pos = atomicAdd(&g_cursor[d], 1);
    g_csr[pos] = s;
}

// K4: xp = fp16(dinv[node] * x[node]), padded to 32 cols. Warp per node,
// lanes 0..15 produce one half2 each.
__global__ void k_pad(const float* __restrict__ x, int n) {
    int idx  = blockIdx.x * blockDim.x + threadIdx.x;
    int node = idx >> 5;
    int c    = idx & 31;
    if (node >= n) return;
    float v  = (c < IND) ? x[node * IND + c] : 0.0f;
    float sv = g_dinv[node] * v;
    // pack pairs: lane c even writes (c, c+1) as half2 via shfl
    float hi = __shfl_down_sync(0xFFFFFFFFu, sv, 1);
    if ((c & 1) == 0)
        g_xp[node * 16 + (c >> 1)] = __floats2half2_rn(sv, hi);
}

// ---------------------------------------------------------------------------
// K5: layer-1 gather. One warp per dst node. Half-warps process two
// neighbors per iteration; each lane loads one half2 (4 B, coalesced).
//   y[d] = dinv[d] * ( xp[d] + sum_{s in in(d)} xp[s] )
// ---------------------------------------------------------------------------
__global__ void k_gather1(int n) {
    int gt   = blockIdx.x * blockDim.x + threadIdx.x;
    int d    = gt >> 5;
    int lane = gt & 31;
    if (d >= n) return;

    int half = lane >> 4;     // 0: neighbor group A, 1: group B
    int p    = lane & 15;     // half2 index within row

    int start = g_rowst[d];
    int cnt   = g_deg[d];

    float ax = 0.0f, ay = 0.0f;
    for (int base = 0; base < cnt; base += 32) {
        int m   = cnt - base; if (m > 32) m = 32;
        int s   = (lane < m) ? g_csr[start + base + lane] : 0;
        int mlo = m < 16 ? m : 16;
        int mhi = m - mlo;
        for (int j = 0; j < mlo; j++) {
            int  sj  = __shfl_sync(0xFFFFFFFFu, s, j + (half << 4));
            bool act = (half == 0) | (j < mhi);
            if (act) {
                float2 v = __half22float2(g_xp[sj * 16 + p]);
                ax += v.x; ay += v.y;
            }
        }
    }
    // combine the two half-warp accumulators
    ax += __shfl_xor_sync(0xFFFFFFFFu, ax, 16);
    ay += __shfl_xor_sync(0xFFFFFFFFu, ay, 16);

    if (half == 0) {
        float2 self = __half22float2(g_xp[d * 16 + p]);
        float di = g_dinv[d];
        float2 o;
        o.x = di * (ax + self.x);
        o.y = di * (ay + self.y);
        *(float2*)&g_aggx[d * PAD + p * 2] = o;
    }
}

// ---------------------------------------------------------------------------
// K6: fused transform. One warp per node:
//   h = relu(y @ W1 + b1);  h2s = dinv * (h @ W2)
// ---------------------------------------------------------------------------
__global__ void k_fused(const float* __restrict__ W1,
                        const float* __restrict__ b1,
                        const float* __restrict__ W2,
                        int n) {
    __shared__ float sW1[IND * HID];
    __shared__ float sb1[HID];
    __shared__ float sW2[HID * 2];
    for (int t = threadIdx.x; t < IND * HID; t += blockDim.x) sW1[t] = W1[t];
    if (threadIdx.x < HID)     sb1[threadIdx.x] = b1[threadIdx.x];
    if (threadIdx.x < HID * 2) sW2[threadIdx.x] = W2[threadIdx.x];
    __syncthreads();

    int gt   = blockIdx.x * blockDim.x + threadIdx.x;
    int node = gt >> 5;
    int lane = gt & 31;
    if (node >= n) return;

    float yv = g_aggx[node * PAD + lane];   // lanes 29..31 zero

    float h0 = sb1[lane];
    float h1 = sb1[lane + 32];
    #pragma unroll
    for (int k = 0; k < IND; k++) {
        float yk = __shfl_sync(0xFFFFFFFFu, yv, k);
        h0 = fmaf(yk, sW1[k * HID + lane],      h0);
        h1 = fmaf(yk, sW1[k * HID + lane + 32], h1);
    }
    h0 = fmaxf(h0, 0.0f);
    h1 = fmaxf(h1, 0.0f);

    float p0 = h0 * sW2[lane * 2]     + h1 * sW2[(lane + 32) * 2];
    float p1 = h0 * sW2[lane * 2 + 1] + h1 * sW2[(lane + 32) * 2 + 1];
    #pragma unroll
    for (int o = 16; o > 0; o >>= 1) {
        p0 += __shfl_xor_sync(0xFFFFFFFFu, p0, o);
        p1 += __shfl_xor_sync(0xFFFFFFFFu, p1, o);
    }
    if (lane == 0) {
        float di = g_dinv[node];
        g_h2[node * 2 + 0] = di * p0;
        g_h2[node * 2 + 1] = di * p1;
    }
}

// ---------------------------------------------------------------------------
// K7: layer-2 gather + output. One warp per dst; lanes strided over edges.
// ---------------------------------------------------------------------------
__global__ void k_gather2(const float* __restrict__ b2,
                          float* __restrict__ out, int n) {
    int gt   = blockIdx.x * blockDim.x + threadIdx.x;
    int d    = gt >> 5;
    int lane = gt & 31;
    if (d >= n) return;

    int start = g_rowst[d];
    int cnt   = g_deg[d];

    float p0 = 0.0f, p1 = 0.0f;
    for (int i = start + lane; i < start + cnt; i += 32) {
        int s = g_csr[i];
        float2 h = *(const float2*)&g_h2[s * 2];
        p0 += h.x;
        p1 += h.y;
    }
    #pragma unroll
    for (int o = 16; o > 0; o >>= 1) {
        p0 += __shfl_xor_sync(0xFFFFFFFFu, p0, o);
        p1 += __shfl_xor_sync(0xFFFFFFFFu, p1, o);
    }
    if (lane == 0) {
        float2 hd = *(const float2*)&g_h2[d * 2];
        float di = g_dinv[d];
        out[d * 2 + 0] = di * (p0 + hd.x) + b2[0];
        out[d * 2 + 1] = di * (p1 + hd.y) + b2[1];
    }
}

// ---------------------------------------------------------------------------
extern "C" void kernel_launch(void* const* d_in, const int* in_sizes, int n_in,
                              void* d_out, int out_size) {
    const float* x  = (const float*)d_in[0];
    const void*  ei = d_in[1];
    const float* W1 = (const float*)d_in[2];
    const float* b1 = (const float*)d_in[3];
    const float* W2 = (const float*)d_in[4];
    const float* b2 = (const float*)d_in[5];
    float*       out = (float*)d_out;

    int n = in_sizes[0] / IND;   // 100000
    int E = in_sizes[1] / 2;     // 3200000
    int nb = (n + 255) / 256;    // 391

    const int TB = 256;
    k_init   <<<(n + TB - 1) / TB, TB>>>((const long long*)ei, n);
    k_count  <<<(E + TB - 1) / TB, TB>>>(ei, E);
    k_scanA  <<<nb, 256>>>(n);
    k_scanB  <<<1, 32>>>(nb);
    k_scanC  <<<nb, 256>>>(n);
    k_scatter<<<(E + TB - 1) / TB, TB>>>(ei, E);
    k_pad    <<<(n * 32 + TB - 1) / TB, TB>>>(x, n);
    k_gather1<<<(n * 32 + TB - 1) / TB, TB>>>(n);
    k_fused  <<<(n * 32 + TB - 1) / TB, TB>>>(W1, b1, W2, n);
    k_gather2<<<(n * 32 + TB - 1) / TB, TB>>>(b2, out, n);
}

// round 5
// speedup vs baseline: 1.8991x; 1.1343x over previous
#include <cuda_runtime.h>
#include <cuda_fp16.h>

// GCN: N=100000, E=3200000, 29 -> 64 -> 2.
// dst-bucketed CSR (count -> block-scan+atomic-ticket alloc -> scatter),
// then gather-only passes. Layer 1 aggregates RAW features (A(xW1)==(Ax)W1)
// stored fp16 (64 B/row), fp32 accumulation, transform fused into gather.
#define NN  100000
#define ME  3200000
#define IND 29
#define HID 64

// ---- scratch (device globals) ----
__device__ int     g_deg    [NN];       // in-degree (real edges only)
__device__ float   g_dinv   [NN];       // rsqrt(deg+1)
__device__ int     g_rowst  [NN];       // CSR row starts (bucket base)
__device__ int     g_cursor [NN];       // insertion cursors
__device__ int     g_csr    [ME];       // src per edge, bucketed by dst
__device__ __half2 g_xp     [NN * 16];  // dinv[s]*x[s] fp16, 16 half2/row
__device__ float   g_h2     [NN * 2];   // dinv[s]*(relu(y W1+b1) W2)
__device__ int     g_total;
__device__ int     g_is64;

// ---------------------------------------------------------------------------
// K0: zero degree counters + ticket; thread 0 detects edge dtype (int32 read
// as int64 packs two indices -> value out of [0,n) almost surely).
// ---------------------------------------------------------------------------
__global__ void k_init(const long long* __restrict__ ei, int n) {
    int i = blockIdx.x * blockDim.x + threadIdx.x;
    if (i < n) g_deg[i] = 0;
    if (i == 0) {
        g_total = 0;
        int is64 = 1;
        #pragma unroll
        for (int t = 0; t < 16; t++) {
            long long v = ei[t];
            if (v < 0 || v >= (long long)n) { is64 = 0; break; }
        }
        g_is64 = is64;
    }
}

// K1: count in-degrees, 2 edges per thread (vectorized index read).
__global__ void k_count(const void* __restrict__ eiv, int E) {
    int i = (blockIdx.x * blockDim.x + threadIdx.x) * 2;
    if (i >= E) return;
    if (g_is64) {
        longlong2 d2 = *(const longlong2*)((const long long*)eiv + E + i);
        atomicAdd(&g_deg[(int)d2.x], 1);
        atomicAdd(&g_deg[(int)d2.y], 1);
    } else {
        int2 d2 = *(const int2*)((const int*)eiv + E + i);
        atomicAdd(&g_deg[d2.x], 1);
        atomicAdd(&g_deg[d2.y], 1);
    }
}

// ---------------------------------------------------------------------------
// K2: bucket allocation — block scan of degrees + one global atomic ticket
// per block for the base. Bucket order across blocks is arbitrary (fine:
// each node's slice stays contiguous & private). Also computes dinv, cursors.
// ---------------------------------------------------------------------------
__global__ void k_alloc(int n) {
    __shared__ int sh[256];
    __shared__ int sbase;
    int t = threadIdx.x;
    int i = blockIdx.x * 256 + t;
    int v = (i < n) ? g_deg[i] : 0;
    sh[t] = v;
    __syncthreads();
    #pragma unroll
    for (int o = 1; o < 256; o <<= 1) {
        int a = (t >= o) ? sh[t - o] : 0;
        __syncthreads();
        sh[t] += a;
        __syncthreads();
    }
    if (t == 255) sbase = atomicAdd(&g_total, sh[255]);
    __syncthreads();
    if (i < n) {
        int rs = sbase + sh[t] - v;
        g_rowst [i] = rs;
        g_cursor[i] = rs;
        g_dinv  [i] = rsqrtf((float)(v + 1));   // +1 self loop
    }
}

// K3: scatter edges into dst-bucketed CSR, 2 edges per thread.
__global__ void k_scatter(const void* __restrict__ eiv, int E) {
    int i = (blockIdx.x * blockDim.x + threadIdx.x) * 2;
    if (i >= E) return;
    int s0, d0, s1, d1;
    if (g_is64) {
        longlong2 s2 = *(const longlong2*)((const long long*)eiv + i);
        longlong2 d2 = *(const longlong2*)((const long long*)eiv + E + i);
        s0 = (int)s2.x; s1 = (int)s2.y; d0 = (int)d2.x; d1 = (int)d2.y;
    } else {
        int2 s2 = *(const int2*)((const int*)eiv + i);
        int2 d2 = *(const int2*)((const int*)eiv + E + i);
        s0 = s2.x; s1 = s2.y; d0 = d2.x; d1 = d2.y;
    }
    g_csr[atomicAdd(&g_cursor[d0], 1)] = s0;
    g_csr[atomicAdd(&g_cursor[d1], 1)] = s1;
}

// K4: xp = fp16(dinv[node] * x[node]), 16 half2 per node (cols 29..31 zero).
__global__ void k_pad(const float* __restrict__ x, int n) {
    int idx  = blockIdx.x * blockDim.x + threadIdx.x;
    int node = idx >> 5;
    int c    = idx & 31;
    if (node >= n) return;
    float v  = (c < IND) ? x[node * IND + c] : 0.0f;
    float sv = g_dinv[node] * v;
    float hi = __shfl_down_sync(0xFFFFFFFFu, sv, 1);
    if ((c & 1) == 0)
        g_xp[node * 16 + (c >> 1)] = __floats2half2_rn(sv, hi);
}

// ---------------------------------------------------------------------------
// K5: FUSED layer-1 gather + transform + layer-2 projection. Warp per node.
//  y = dinv[d]*(xp[d] + sum_s xp[s])  -- gather: half-warps take 2 neighbors
//      per step; inner loop FIXED 16 iters, predicated loads -> deep MLP.
//  h = relu(y @ W1 + b1);  h2s = dinv[d] * (h @ W2)   (y never leaves regs)
// ---------------------------------------------------------------------------
__global__ void __launch_bounds__(512) k_gfused(const float* __restrict__ W1,
                                                const float* __restrict__ b1,
                                                const float* __restrict__ W2,
                                                int n) {
    __shared__ float sW1[IND * HID];
    __shared__ float sb1[HID];
    __shared__ float sW2[HID * 2];
    for (int t = threadIdx.x; t < IND * HID; t += blockDim.x) sW1[t] = W1[t];
    if (threadIdx.x < HID)     sb1[threadIdx.x] = b1[threadIdx.x];
    if (threadIdx.x < HID * 2) sW2[threadIdx.x] = W2[threadIdx.x];
    __syncthreads();

    int gt   = blockIdx.x * blockDim.x + threadIdx.x;
    int d    = gt >> 5;
    int lane = gt & 31;
    if (d >= n) return;

    int half = lane >> 4;      // neighbor group A/B
    int p    = lane & 15;      // half2 column index
    int hb   = half << 4;

    int start = g_rowst[d];
    int cnt   = g_deg[d];

    float ax = 0.0f, ay = 0.0f;
    for (int base = 0; base < cnt; base += 32) {
        int idx = base + lane;
        int s   = (idx < cnt) ? g_csr[start + idx] : 0;
        #pragma unroll
        for (int j = 0; j < 16; j++) {
            int sj = __shfl_sync(0xFFFFFFFFu, s, hb | j);
            if (base + hb + j < cnt) {                  // predicated load
                float2 v = __half22float2(g_xp[sj * 16 + p]);
                ax += v.x; ay += v.y;
            }
        }
    }
    ax += __shfl_xor_sync(0xFFFFFFFFu, ax, 16);
    ay += __shfl_xor_sync(0xFFFFFFFFu, ay, 16);

    float2 self = __half22float2(g_xp[d * 16 + p]);
    float  di   = g_dinv[d];
    ax = di * (ax + self.x);    // y[2p]
    ay = di * (ay + self.y);    // y[2p+1]

    // transform: broadcast y pairs from lanes 0..14, FMA against W1 rows.
    float h0 = sb1[lane];
    float h1 = sb1[lane + 32];
    #pragma unroll
    for (int kp = 0; kp < 15; kp++) {
        float ya = __shfl_sync(0xFFFFFFFFu, ax, kp);   // col 2kp
        float yb = __shfl_sync(0xFFFFFFFFu, ay, kp);   // col 2kp+1
        h0 = fmaf(ya, sW1[(2 * kp) * HID + lane],      h0);
        h1 = fmaf(ya, sW1[(2 * kp) * HID + lane + 32], h1);
        if (2 * kp + 1 < IND) {
            h0 = fmaf(yb, sW1[(2 * kp + 1) * HID + lane],      h0);
            h1 = fmaf(yb, sW1[(2 * kp + 1) * HID + lane + 32], h1);
        }
    }
    h0 = fmaxf(h0, 0.0f);
    h1 = fmaxf(h1, 0.0f);

    float p0 = h0 * sW2[lane * 2]     + h1 * sW2[(lane + 32) * 2];
    float p1 = h0 * sW2[lane * 2 + 1] + h1 * sW2[(lane + 32) * 2 + 1];
    #pragma unroll
    for (int o = 16; o > 0; o >>= 1) {
        p0 += __shfl_xor_sync(0xFFFFFFFFu, p0, o);
        p1 += __shfl_xor_sync(0xFFFFFFFFu, p1, o);
    }
    if (lane == 0) {
        g_h2[d * 2 + 0] = di * p0;
        g_h2[d * 2 + 1] = di * p1;
    }
}

// ---------------------------------------------------------------------------
// K6: layer-2 gather + output. Warp per dst; lanes strided over edges.
// ---------------------------------------------------------------------------
__global__ void k_gather2(const float* __restrict__ b2,
                          float* __restrict__ out, int n) {
    int gt   = blockIdx.x * blockDim.x + threadIdx.x;
    int d    = gt >> 5;
    int lane = gt & 31;
    if (d >= n) return;

    int start = g_rowst[d];
    int cnt   = g_deg[d];

    float p0 = 0.0f, p1 = 0.0f;
    for (int i = lane; i < cnt; i += 32) {
        int s = g_csr[start + i];
        float2 h = *(const float2*)&g_h2[s * 2];
        p0 += h.x;
        p1 += h.y;
    }
    #pragma unroll
    for (int o = 16; o > 0; o >>= 1) {
        p0 += __shfl_xor_sync(0xFFFFFFFFu, p0, o);
        p1 += __shfl_xor_sync(0xFFFFFFFFu, p1, o);
    }
    if (lane == 0) {
        float2 hd = *(const float2*)&g_h2[d * 2];
        float di = g_dinv[d];
        out[d * 2 + 0] = di * (p0 + hd.x) + b2[0];
        out[d * 2 + 1] = di * (p1 + hd.y) + b2[1];
    }
}

// ---------------------------------------------------------------------------
extern "C" void kernel_launch(void* const* d_in, const int* in_sizes, int n_in,
                              void* d_out, int out_size) {
    const float* x  = (const float*)d_in[0];
    const void*  ei = d_in[1];
    const float* W1 = (const float*)d_in[2];
    const float* b1 = (const float*)d_in[3];
    const float* W2 = (const float*)d_in[4];
    const float* b2 = (const float*)d_in[5];
    float*       out = (float*)d_out;

    int n = in_sizes[0] / IND;   // 100000
    int E = in_sizes[1] / 2;     // 3200000
    int nb = (n + 255) / 256;    // 391
    int Eh = E / 2;

    const int TB = 256;
    k_init   <<<(n + TB - 1) / TB, TB>>>((const long long*)ei, n);
    k_count  <<<(Eh + TB - 1) / TB, TB>>>(ei, E);
    k_alloc  <<<nb, 256>>>(n);
    k_scatter<<<(Eh + TB - 1) / TB, TB>>>(ei, E);
    k_pad    <<<(n * 32 + TB - 1) / TB, TB>>>(x, n);
    k_gfused <<<(n * 32 + 511) / 512, 512>>>(W1, b1, W2, n);
    k_gather2<<<(n * 32 + TB - 1) / TB, TB>>>(b2, out, n);
}